// round 7
// baseline (speedup 1.0000x reference)
#include <cuda_runtime.h>
#include <cstdint>

// Problem constants (static shapes from reference)
#define CC   64          // channels
#define CINN 66          // channels + 2 coord planes
#define HH   160
#define WW   256
#define LL   (HH * WW)   // 40960 pixels
#define TP   256         // pixels per tile = one full image row
#define NTHREADS 256
#define NINST 32         // 4 images * 8 instances
#define NPARAMS 8513

// param layout offsets
#define OFF_W0 0
#define OFF_W1 4224
#define OFF_W2 8320
#define OFF_B0 8384
#define OFF_B1 8448
#define OFF_B2 8512
#define MASK_BIAS_SHIFT 2.19f

// smem layout (floats), all section bases multiples of 4 floats (16B aligned):
//  sW0t : transposed W0 [k<66][o<64], stride 68  -> 4488
//  sW1t : transposed W1 [k<64][o<64], stride 68  -> 4352  (base 4488)
//  sXH  : X [k<66][p<256] stride 256 -> 16896 (base 8840), aliased later
//         as H [o<64][p<256] stride 256
//  misc : sw2/sb0/sb1 64 each + sb2 + pad       (base 25736)
#define SWT_STRIDE 68
#define SW0T_BASE  0
#define SW1T_BASE  4488
#define SXH_BASE   8840
#define SROW       256
#define MISC_BASE  25736
#define SMEM_FLOATS (MISC_BASE + 64*3 + 4)
#define SMEM_BYTES  (SMEM_FLOATS * 4)

__device__ __forceinline__ unsigned long long pack2(float a, float b) {
    unsigned long long r;
    asm("mov.b64 %0, {%1,%2};" : "=l"(r) : "f"(a), "f"(b));
    return r;
}
__device__ __forceinline__ void fma2(unsigned long long& d, unsigned long long a, unsigned long long b) {
    asm("fma.rn.f32x2 %0, %1, %2, %0;" : "+l"(d) : "l"(a), "l"(b));
}
__device__ __forceinline__ float2 unpack2(unsigned long long v) {
    float2 f;
    asm("mov.b64 {%0,%1}, %2;" : "=f"(f.x), "=f"(f.y) : "l"(v));
    return f;
}

extern __shared__ __align__(16) float smem[];

__global__ __launch_bounds__(NTHREADS, 2)
void condlane_fused_kernel(const float* __restrict__ x,
                           const float* __restrict__ params,
                           float* __restrict__ out)
{
    float* sW0t = smem + SW0T_BASE;
    float* sW1t = smem + SW1T_BASE;
    float* sXH  = smem + SXH_BASE;
    float* sw2  = smem + MISC_BASE;
    float* sb0  = smem + MISC_BASE + 64;
    float* sb1  = smem + MISC_BASE + 128;
    float* sb2  = smem + MISC_BASE + 192;

    const int tile = blockIdx.x;   // 0..159  (image row)
    const int inst = blockIdx.y;   // 0..31
    const int img  = inst >> 3;    // 8 instances per image (static num_ins)
    const int tid  = threadIdx.x;  // 0..255

    const float* p = params + (size_t)inst * NPARAMS;

    // ---- W0 [64 o][66 c] -> sW0t[c][o] (transposed; adjacent rows adjacent) ----
    for (int idx = tid; idx < 64 * 66; idx += NTHREADS) {
        int o = idx / 66;
        int c = idx - o * 66;
        sW0t[c * SWT_STRIDE + o] = p[OFF_W0 + idx];
    }
    // ---- W1 [64][64] -> sW1t[c][o] ----
    for (int idx = tid; idx < 64 * 64; idx += NTHREADS) {
        int o = idx >> 6;
        int c = idx & 63;
        sW1t[c * SWT_STRIDE + o] = p[OFF_W1 + idx];
    }
    if (tid < 64) {
        sw2[tid] = p[OFF_W2 + tid];
        sb0[tid] = p[OFF_B0 + tid];
        sb1[tid] = p[OFF_B1 + tid];
    }
    if (tid == 0) sb2[0] = p[OFF_B2] - MASK_BIAS_SHIFT;

    // ---- build X tile [66][256]: row 0 = x-coords (0..255), row 1 = y ----
    const int l0 = tile * TP;                // start pixel; tile == y coordinate
    if (tid < TP) {
        sXH[tid]        = (float)tid;        // x coord (full row)
        sXH[SROW + tid] = (float)tile;       // y coord
    }
    {
        const float* xb = x + (size_t)img * CC * LL + l0;
        #pragma unroll
        for (int i = 0; i < 16; i++) {
            int f4 = i * NTHREADS + tid;     // 0..4095
            int ch = f4 >> 6;                // 0..63
            int c4 = (f4 & 63) * 4;          // 0..252
            float4 v = *(const float4*)(xb + (size_t)ch * LL + c4);
            *(float4*)(sXH + (2 + ch) * SROW + c4) = v;
        }
    }
    __syncthreads();

    // ---- warp tiling: warp w -> rows 16*(w&3) .. +15 ; pixel half (w>>2)*128 ----
    const int wid  = tid >> 5;
    const int lane = tid & 31;
    const int ro   = (wid & 3) * 16;                // 16 rows = 8 row-pairs
    const int pco  = (wid >> 2) * 128 + lane * 4;   // 4 consecutive pixels

    // acc[pair r][pixel j] = (h[ro+2r][pj], h[ro+2r+1][pj]), bias pre-loaded
    unsigned long long acc[8][4];
    #pragma unroll
    for (int r = 0; r < 8; r++) {
        unsigned long long b = pack2(sb0[ro + 2 * r], sb0[ro + 2 * r + 1]);
        acc[r][0] = b; acc[r][1] = b; acc[r][2] = b; acc[r][3] = b;
    }

    // ======== GEMM1: hdn0 = W0 @ X  (K = 66) ========
    #pragma unroll 1
    for (int k = 0; k < CINN; k++) {
        float4 xv = *(const float4*)(sXH + k * SROW + pco);
        const float* wk = sW0t + k * SWT_STRIDE + ro;
        ulonglong2 wA = *(const ulonglong2*)(wk);        // pairs 0,1
        ulonglong2 wB = *(const ulonglong2*)(wk + 4);    // pairs 2,3
        ulonglong2 wC = *(const ulonglong2*)(wk + 8);    // pairs 4,5
        ulonglong2 wD = *(const ulonglong2*)(wk + 12);   // pairs 6,7
        unsigned long long xp0 = pack2(xv.x, xv.x);
        unsigned long long xp1 = pack2(xv.y, xv.y);
        unsigned long long xp2 = pack2(xv.z, xv.z);
        unsigned long long xp3 = pack2(xv.w, xv.w);
        fma2(acc[0][0], wA.x, xp0); fma2(acc[0][1], wA.x, xp1);
        fma2(acc[0][2], wA.x, xp2); fma2(acc[0][3], wA.x, xp3);
        fma2(acc[1][0], wA.y, xp0); fma2(acc[1][1], wA.y, xp1);
        fma2(acc[1][2], wA.y, xp2); fma2(acc[1][3], wA.y, xp3);
        fma2(acc[2][0], wB.x, xp0); fma2(acc[2][1], wB.x, xp1);
        fma2(acc[2][2], wB.x, xp2); fma2(acc[2][3], wB.x, xp3);
        fma2(acc[3][0], wB.y, xp0); fma2(acc[3][1], wB.y, xp1);
        fma2(acc[3][2], wB.y, xp2); fma2(acc[3][3], wB.y, xp3);
        fma2(acc[4][0], wC.x, xp0); fma2(acc[4][1], wC.x, xp1);
        fma2(acc[4][2], wC.x, xp2); fma2(acc[4][3], wC.x, xp3);
        fma2(acc[5][0], wC.y, xp0); fma2(acc[5][1], wC.y, xp1);
        fma2(acc[5][2], wC.y, xp2); fma2(acc[5][3], wC.y, xp3);
        fma2(acc[6][0], wD.x, xp0); fma2(acc[6][1], wD.x, xp1);
        fma2(acc[6][2], wD.x, xp2); fma2(acc[6][3], wD.x, xp3);
        fma2(acc[7][0], wD.y, xp0); fma2(acc[7][1], wD.y, xp1);
        fma2(acc[7][2], wD.y, xp2); fma2(acc[7][3], wD.y, xp3);
    }
    __syncthreads();   // everyone done reading X before H overwrites it

    // relu (bias already in acc) -> H (aliased onto X buffer)
    #pragma unroll
    for (int r = 0; r < 8; r++) {
        float2 t0 = unpack2(acc[r][0]);
        float2 t1 = unpack2(acc[r][1]);
        float2 t2 = unpack2(acc[r][2]);
        float2 t3 = unpack2(acc[r][3]);
        float4 vlo = make_float4(t0.x, t1.x, t2.x, t3.x);
        float4 vhi = make_float4(t0.y, t1.y, t2.y, t3.y);
        vlo.x = vlo.x > 0.f ? vlo.x : 0.f;  vlo.y = vlo.y > 0.f ? vlo.y : 0.f;
        vlo.z = vlo.z > 0.f ? vlo.z : 0.f;  vlo.w = vlo.w > 0.f ? vlo.w : 0.f;
        vhi.x = vhi.x > 0.f ? vhi.x : 0.f;  vhi.y = vhi.y > 0.f ? vhi.y : 0.f;
        vhi.z = vhi.z > 0.f ? vhi.z : 0.f;  vhi.w = vhi.w > 0.f ? vhi.w : 0.f;
        *(float4*)(sXH + (ro + 2 * r) * SROW + pco)     = vlo;
        *(float4*)(sXH + (ro + 2 * r + 1) * SROW + pco) = vhi;
    }
    __syncthreads();

    // ======== GEMM2: hdn1 = W1 @ relu(hdn0)  (K = 64) ========
    #pragma unroll
    for (int r = 0; r < 8; r++) {
        unsigned long long b = pack2(sb1[ro + 2 * r], sb1[ro + 2 * r + 1]);
        acc[r][0] = b; acc[r][1] = b; acc[r][2] = b; acc[r][3] = b;
    }

    #pragma unroll 1
    for (int k = 0; k < CC; k++) {
        float4 xv = *(const float4*)(sXH + k * SROW + pco);
        const float* wk = sW1t + k * SWT_STRIDE + ro;
        ulonglong2 wA = *(const ulonglong2*)(wk);
        ulonglong2 wB = *(const ulonglong2*)(wk + 4);
        ulonglong2 wC = *(const ulonglong2*)(wk + 8);
        ulonglong2 wD = *(const ulonglong2*)(wk + 12);
        unsigned long long xp0 = pack2(xv.x, xv.x);
        unsigned long long xp1 = pack2(xv.y, xv.y);
        unsigned long long xp2 = pack2(xv.z, xv.z);
        unsigned long long xp3 = pack2(xv.w, xv.w);
        fma2(acc[0][0], wA.x, xp0); fma2(acc[0][1], wA.x, xp1);
        fma2(acc[0][2], wA.x, xp2); fma2(acc[0][3], wA.x, xp3);
        fma2(acc[1][0], wA.y, xp0); fma2(acc[1][1], wA.y, xp1);
        fma2(acc[1][2], wA.y, xp2); fma2(acc[1][3], wA.y, xp3);
        fma2(acc[2][0], wB.x, xp0); fma2(acc[2][1], wB.x, xp1);
        fma2(acc[2][2], wB.x, xp2); fma2(acc[2][3], wB.x, xp3);
        fma2(acc[3][0], wB.y, xp0); fma2(acc[3][1], wB.y, xp1);
        fma2(acc[3][2], wB.y, xp2); fma2(acc[3][3], wB.y, xp3);
        fma2(acc[4][0], wC.x, xp0); fma2(acc[4][1], wC.x, xp1);
        fma2(acc[4][2], wC.x, xp2); fma2(acc[4][3], wC.x, xp3);
        fma2(acc[5][0], wC.y, xp0); fma2(acc[5][1], wC.y, xp1);
        fma2(acc[5][2], wC.y, xp2); fma2(acc[5][3], wC.y, xp3);
        fma2(acc[6][0], wD.x, xp0); fma2(acc[6][1], wD.x, xp1);
        fma2(acc[6][2], wD.x, xp2); fma2(acc[6][3], wD.x, xp3);
        fma2(acc[7][0], wD.y, xp0); fma2(acc[7][1], wD.y, xp1);
        fma2(acc[7][2], wD.y, xp2); fma2(acc[7][3], wD.y, xp3);
    }
    __syncthreads();   // all reads of H done before overwrite

    // relu -> H (reuse)
    #pragma unroll
    for (int r = 0; r < 8; r++) {
        float2 t0 = unpack2(acc[r][0]);
        float2 t1 = unpack2(acc[r][1]);
        float2 t2 = unpack2(acc[r][2]);
        float2 t3 = unpack2(acc[r][3]);
        float4 vlo = make_float4(t0.x, t1.x, t2.x, t3.x);
        float4 vhi = make_float4(t0.y, t1.y, t2.y, t3.y);
        vlo.x = vlo.x > 0.f ? vlo.x : 0.f;  vlo.y = vlo.y > 0.f ? vlo.y : 0.f;
        vlo.z = vlo.z > 0.f ? vlo.z : 0.f;  vlo.w = vlo.w > 0.f ? vlo.w : 0.f;
        vhi.x = vhi.x > 0.f ? vhi.x : 0.f;  vhi.y = vhi.y > 0.f ? vhi.y : 0.f;
        vhi.z = vhi.z > 0.f ? vhi.z : 0.f;  vhi.w = vhi.w > 0.f ? vhi.w : 0.f;
        *(float4*)(sXH + (ro + 2 * r) * SROW + pco)     = vlo;
        *(float4*)(sXH + (ro + 2 * r + 1) * SROW + pco) = vhi;
    }
    __syncthreads();

    // ======== Layer 3: out[p] = w2 . hdn1[:,p] + b2 ========
    {
        float a3 = sb2[0];
        #pragma unroll
        for (int o = 0; o < CC; o++)
            a3 = fmaf(sw2[o], sXH[o * SROW + tid], a3);
        out[(size_t)inst * LL + l0 + tid] = a3;
    }
}

extern "C" void kernel_launch(void* const* d_in, const int* in_sizes, int n_in,
                              void* d_out, int out_size)
{
    const float* x      = (const float*)d_in[0];   // [4,64,160,256] fp32
    const float* params = (const float*)d_in[1];   // [32,8513] fp32
    // d_in[2] = num_ins (static 8 per image, unused)
    float* out = (float*)d_out;                    // [1,32,160,256] fp32

    (void)in_sizes; (void)n_in; (void)out_size;

    cudaFuncSetAttribute(condlane_fused_kernel,
                         cudaFuncAttributeMaxDynamicSharedMemorySize, SMEM_BYTES);

    dim3 grid(LL / TP, NINST);   // 160 x 32 = 5120 blocks
    condlane_fused_kernel<<<grid, NTHREADS, SMEM_BYTES>>>(x, params, out);
}